// round 9
// baseline (speedup 1.0000x reference)
#include <cuda_runtime.h>
#include <cuda_fp16.h>
#include <cstdint>

#define IN_F  4096
#define OUT_F 4096
#define NFAC  3

// ---------------- scratch (device globals; allocation forbidden) -----------
__device__ __align__(1024) float  g_Q[NFAC * 64 * 64 * 64];
__device__ int    g_pinv[NFAC * IN_F];
__device__ __align__(1024) float  g_w0[(size_t)OUT_F * IN_F];        // 64 MB
__device__ __align__(1024) __half g_wh[(size_t)OUT_F * IN_F];        // 32 MB
__device__ __align__(1024) __half g_xh[(size_t)8 * 2048 * IN_F];     // 128 MB

// ---------------- helpers ---------------------------------------------------
__device__ __forceinline__ uint32_t smem_u32(const void* p) {
    uint32_t a;
    asm("{ .reg .u64 t; cvta.to.shared.u64 t, %1; cvt.u32.u64 %0, t; }" : "=r"(a) : "l"(p));
    return a;
}
#define CP_ASYNC16(dst, src) \
    asm volatile("cp.async.cg.shared.global [%0], [%1], 16;" :: "r"(dst), "l"(src) : "memory")
#define CP_COMMIT()  asm volatile("cp.async.commit_group;" ::: "memory")
#define CP_WAIT1()   asm volatile("cp.async.wait_group 1;" ::: "memory")

#define LDSM4(r, addr) \
    asm volatile("ldmatrix.sync.aligned.m8n8.x4.shared.b16 {%0,%1,%2,%3}, [%4];" \
        : "=r"((r)[0]), "=r"((r)[1]), "=r"((r)[2]), "=r"((r)[3]) : "r"(addr))

#define MMA16816(c, a, b0v, b1v) \
    asm volatile("mma.sync.aligned.m16n8k16.row.col.f32.f16.f16.f32 " \
        "{%0,%1,%2,%3},{%4,%5,%6,%7},{%8,%9},{%0,%1,%2,%3};" \
        : "+f"((c)[0]), "+f"((c)[1]), "+f"((c)[2]), "+f"((c)[3]) \
        : "r"((a)[0]), "r"((a)[1]), "r"((a)[2]), "r"((a)[3]), "r"(b0v), "r"(b1v))

// ---- fused prep: Cayley (0..191) | pinv (192) | x->fp16 (193..) -----------
__global__ void prep_kernel(const float* __restrict__ R_all,
                            const int* __restrict__ perm,
                            const float4* __restrict__ xin,
                            uint4* __restrict__ xout)
{
    const int tid = threadIdx.x;
    const int bid = blockIdx.x;

    if (bid > 192) {                 // x conversion: one uint4 out per thread
        int i = (bid - 193) * 256 + tid;
        float4 a = xin[2 * i], b = xin[2 * i + 1];
        __half2 h0 = __floats2half2_rn(a.x, a.y);
        __half2 h1 = __floats2half2_rn(a.z, a.w);
        __half2 h2 = __floats2half2_rn(b.x, b.y);
        __half2 h3 = __floats2half2_rn(b.z, b.w);
        uint4 v;
        v.x = *(uint32_t*)&h0; v.y = *(uint32_t*)&h1;
        v.z = *(uint32_t*)&h2; v.w = *(uint32_t*)&h3;
        xout[i] = v;
        return;
    }
    if (bid == 192) {                // inverse permutation
        for (int idx = tid; idx < NFAC * IN_F; idx += 256) {
            int f = idx >> 12, j = idx & 4095;
            g_pinv[(f << 12) + perm[idx]] = j;
        }
        return;
    }

    // Cayley: Q = (I-S)(I+S)^-1 via GJ on [I-S | I+S]
    __shared__ float aug[64][129];
    const float* R = R_all + (size_t)bid * 4096;

    for (int idx = tid; idx < 4096; idx += 256) {
        int i = idx >> 6, j = idx & 63;
        float s = 0.5f * (R[i * 64 + j] - R[j * 64 + i]);
        float d = (i == j) ? 1.0f : 0.0f;
        aug[i][j]      = d - s;
        aug[i][64 + j] = d + s;
    }
    __syncthreads();

    const int r  = tid >> 2;
    const int c0 = tid & 3;
    for (int k = 0; k < 64; k++) {
        float inv = 1.0f / aug[k][k];
        __syncthreads();
        if (tid < 32) {
            #pragma unroll
            for (int i = 0; i < 4; i++) aug[k][tid + 32 * i] *= inv;
        }
        __syncthreads();
        float f = aug[r][k];
        __syncthreads();
        if (r != k) {
            #pragma unroll
            for (int i = 0; i < 32; i++) {
                int c = c0 + 4 * i;
                aug[r][c] -= f * aug[k][c];
            }
        }
        __syncthreads();
    }

    float* Qm = g_Q + (size_t)bid * 4096;
    for (int idx = tid; idx < 4096; idx += 256) {
        int a = idx >> 6, b = idx & 63;
        Qm[a * 64 + b] = aug[b][64 + a];
    }
}

// ------- fused butterfly factors 0+1 on a 128-col x 128-row tile -----------
#define ROT01_SMEM (128*132*4 + 2*64*68*4 + 2*128*4)

__global__ __launch_bounds__(256) void rot01_kernel(
    const float* __restrict__ Win, float* __restrict__ Wout)
{
    extern __shared__ char sm01[];
    float (*T)[132]      = (float (*)[132])sm01;
    float (*Qs)[64][68]  = (float (*)[64][68])(sm01 + 128 * 132 * 4);
    int*   lsrc          = (int*)(sm01 + 128 * 132 * 4 + 2 * 64 * 68 * 4);

    const int g    = blockIdx.x;
    const int rg   = blockIdx.y;
    const int tid  = threadIdx.x;
    const int col0 = g * 128;
    const int row0 = rg * 128;

    #pragma unroll
    for (int i = 0; i < 16; i++) {
        int q = tid + 256 * i;
        int rr = q >> 5, c4 = (q & 31) * 4;
        *(float4*)&T[rr][c4] = *(const float4*)&Win[(size_t)(row0 + rr) * IN_F + col0 + c4];
    }
    if (tid < 128) {
        lsrc[tid]       = g_pinv[col0 + tid] - col0;
        lsrc[128 + tid] = g_pinv[4096 + col0 + tid] - col0;
    }

    const int c  = tid & 127, sb = c >> 6, a = c & 63;
    const int half = tid >> 7;

    #pragma unroll 1
    for (int f = 0; f < 2; f++) {
        __syncthreads();
        for (int i = 0; i < 32; i++) {
            int q = tid + 256 * i;
            int blk = q >> 12, rem = q & 4095;
            Qs[blk][rem >> 6][rem & 63] =
                g_Q[((size_t)f * 64 + 2 * g + blk) * 4096 + rem];
        }
        __syncthreads();

        const int ldst = lsrc[f * 128 + c];
        #pragma unroll 1
        for (int ch = 0; ch < 4; ch++) {
            const int rowb = half * 64 + ch * 16;
            float acc[16];
            #pragma unroll
            for (int j = 0; j < 16; j++) acc[j] = 0.0f;
            #pragma unroll
            for (int b4 = 0; b4 < 16; b4++) {
                float4 qv = *(const float4*)&Qs[sb][a][b4 * 4];
                int src = lsrc[f * 128 + sb * 64 + b4 * 4];
                #pragma unroll
                for (int j = 0; j < 16; j++) {
                    float4 t = *(const float4*)&T[rowb + j][src];
                    acc[j] += qv.x * t.x + qv.y * t.y + qv.z * t.z + qv.w * t.w;
                }
            }
            __syncthreads();
            #pragma unroll
            for (int j = 0; j < 16; j++) T[rowb + j][ldst] = acc[j];
            __syncthreads();
        }
    }

    #pragma unroll
    for (int i = 0; i < 16; i++) {
        int q = tid + 256 * i;
        int rr = q >> 5, c4 = (q & 31) * 4;
        *(float4*)&Wout[(size_t)(row0 + rr) * IN_F + col0 + c4] = *(float4*)&T[rr][c4];
    }
}

// ---------------- factor 2 + scale + fp16 emit (proven kernel) -------------
__global__ __launch_bounds__(256) void rot_kernel(
    const float* __restrict__ Win, float* __restrict__ Wout,
    __half* __restrict__ Wh, int factor, const float* __restrict__ s)
{
    __shared__ float Qs[64][68];
    __shared__ float Ts[64][68];
    __shared__ int   cs[64];

    const int d   = blockIdx.x;
    const int rg  = blockIdx.y;
    const int tid = threadIdx.x;

    const float* Qm = g_Q + ((size_t)factor * 64 + d) * 4096;
    #pragma unroll
    for (int i = 0; i < 4; i++) {
        int q = tid + 256 * i;
        int row = q >> 4, c4 = (q & 15) * 4;
        *(float4*)&Qs[row][c4] = *(const float4*)&Qm[row * 64 + c4];
    }
    if (tid < 64) cs[tid] = g_pinv[factor * IN_F + d * 64 + tid];
    __syncthreads();

    const int row0 = rg * 64;
    #pragma unroll
    for (int i = 0; i < 4; i++) {
        int q = tid + 256 * i;
        int rr = q >> 4, b0 = (q & 15) * 4;
        *(float4*)&Ts[rr][b0] = *(const float4*)&Win[(size_t)(row0 + rr) * IN_F + cs[b0]];
    }
    __syncthreads();

    const int a  = tid & 63;
    const int r0 = tid >> 6;
    float acc[16];
    #pragma unroll
    for (int j = 0; j < 16; j++) acc[j] = 0.0f;

    for (int b4 = 0; b4 < 16; b4++) {
        float4 q = *(const float4*)&Qs[a][b4 * 4];
        #pragma unroll
        for (int j = 0; j < 16; j++) {
            float4 t = *(const float4*)&Ts[r0 * 16 + j][b4 * 4];
            acc[j] += q.x * t.x + q.y * t.y + q.z * t.z + q.w * t.w;
        }
    }

    const int col = cs[a];
    #pragma unroll
    for (int j = 0; j < 16; j++) {
        int rr = row0 + r0 * 16 + j;
        if (s) Wh[(size_t)rr * IN_F + col] = __float2half_rn(acc[j] * s[rr]);
        else   Wout[(size_t)rr * IN_F + col] = acc[j];
    }
}

// ---------------- fp16 mma.sync GEMM: C[16384,4096] = A * B^T + bias -------
// CTA 128x128, 4 warps (2x2), warp tile 64x64, BK=64, 3 stages, 2 CTAs/SM.
// kt body: kk0 LDSMs -> issue next stage cp.async -> MMAs (loads overlap MMAs)
#define BKH 64
#define AST 16384
#define STG 32768
#define STAGES 3
#define SMEM_TOTAL (STAGES * STG)       // 98304

__global__ __launch_bounds__(128, 2) void gemm_hmma(
    const __half* __restrict__ A, const __half* __restrict__ B,
    const float* __restrict__ bias, float* __restrict__ C)
{
    extern __shared__ char smem[];
    const uint32_t sb = smem_u32(smem);
    const int tid = threadIdx.x;
    const int wid = tid >> 5, lid = tid & 31;
    const int wm  = wid >> 1, wn = wid & 1;
    const int m0  = blockIdx.y * 128;
    const int n0  = blockIdx.x * 128;

    float acc[4][4][2][4];
    #pragma unroll
    for (int mi = 0; mi < 4; mi++)
        #pragma unroll
        for (int g = 0; g < 4; g++)
            #pragma unroll
            for (int j = 0; j < 2; j++)
                #pragma unroll
                for (int k = 0; k < 4; k++) acc[mi][g][j][k] = 0.0f;

    auto load_stage = [&](int st, int kt) {
        const uint32_t ab = sb + st * STG;
        const uint32_t bb = ab + AST;
        const __half* Ag = A + (size_t)m0 * IN_F + kt * BKH;
        const __half* Bg = B + (size_t)n0 * IN_F + kt * BKH;
        #pragma unroll
        for (int i = 0; i < 8; i++) {
            int q = tid + 128 * i;
            int r = q >> 3, c = q & 7;
            CP_ASYNC16(ab + r * 128 + ((c ^ (r & 7)) << 4), Ag + (size_t)r * IN_F + c * 8);
        }
        #pragma unroll
        for (int i = 0; i < 8; i++) {
            int q = tid + 128 * i;
            int r = q >> 3, c = q & 7;
            CP_ASYNC16(bb + r * 128 + ((c ^ (r & 7)) << 4), Bg + (size_t)r * IN_F + c * 8);
        }
    };

    load_stage(0, 0); CP_COMMIT();
    load_stage(1, 1); CP_COMMIT();

    const int lrow = (lid & 7) + ((lid >> 3) & 1) * 8;
    const int lkhi = (lid >> 4) & 1;
    const int rowx = lrow & 7;

    const int NK = IN_F / BKH;    // 64
    for (int kt = 0; kt < NK; kt++) {
        CP_WAIT1();
        __syncthreads();
        const uint32_t as = sb + (kt % STAGES) * STG;
        const uint32_t bs = as + AST;
        const uint32_t a_base = as + (wm * 64 + lrow) * 128;
        const uint32_t b_base = bs + (wn * 64 + lrow) * 128;

        // --- kk = 0: LDSM first, then kick off next stage's loads ---
        uint32_t afr[4][4], bfr[4][4];
        {
            const uint32_t coff = ((lkhi ^ rowx) << 4);
            #pragma unroll
            for (int mi = 0; mi < 4; mi++)
                LDSM4(afr[mi], a_base + mi * 2048 + coff);
            #pragma unroll
            for (int g = 0; g < 4; g++)
                LDSM4(bfr[g], b_base + g * 2048 + coff);
        }
        if (kt + 2 < NK) load_stage((kt + 2) % STAGES, kt + 2);
        CP_COMMIT();
        #pragma unroll
        for (int mi = 0; mi < 4; mi++)
            #pragma unroll
            for (int g = 0; g < 4; g++) {
                MMA16816(acc[mi][g][0], afr[mi], bfr[g][0], bfr[g][2]);
                MMA16816(acc[mi][g][1], afr[mi], bfr[g][1], bfr[g][3]);
            }

        // --- kk = 1..3 ---
        #pragma unroll
        for (int kk = 1; kk < 4; kk++) {
            const uint32_t coff = ((((kk << 1) | lkhi) ^ rowx) << 4);
            #pragma unroll
            for (int mi = 0; mi < 4; mi++)
                LDSM4(afr[mi], a_base + mi * 2048 + coff);
            #pragma unroll
            for (int g = 0; g < 4; g++)
                LDSM4(bfr[g], b_base + g * 2048 + coff);
            #pragma unroll
            for (int mi = 0; mi < 4; mi++)
                #pragma unroll
                for (int g = 0; g < 4; g++) {
                    MMA16816(acc[mi][g][0], afr[mi], bfr[g][0], bfr[g][2]);
                    MMA16816(acc[mi][g][1], afr[mi], bfr[g][1], bfr[g][3]);
                }
        }
    }

    // epilogue: fused bias, float2 stores
    const int mrow = lid >> 2;
    const int ncl  = (lid & 3) * 2;
    #pragma unroll
    for (int g = 0; g < 4; g++)
        #pragma unroll
        for (int j = 0; j < 2; j++) {
            int n = n0 + wn * 64 + g * 16 + j * 8 + ncl;
            float2 bv = *(const float2*)&bias[n];
            #pragma unroll
            for (int mi = 0; mi < 4; mi++) {
                int m = m0 + wm * 64 + mi * 16 + mrow;
                float* a4 = acc[mi][g][j];
                float2 v0 = { a4[0] + bv.x, a4[1] + bv.y };
                float2 v1 = { a4[2] + bv.x, a4[3] + bv.y };
                *(float2*)&C[(size_t)m * OUT_F + n]       = v0;
                *(float2*)&C[(size_t)(m + 8) * OUT_F + n] = v1;
            }
        }
}

// ---------------- launch ----------------
extern "C" void kernel_launch(void* const* d_in, const int* in_sizes, int n_in,
                              void* d_out, int out_size)
{
    const float* x      = (const float*)d_in[0];
    const float* weight = (const float*)d_in[1];
    const float* bias   = (const float*)d_in[2];
    const float* boft_R = (const float*)d_in[3];
    const float* boft_s = (const float*)d_in[4];
    const int*   perm   = (const int*)d_in[5];
    float* out = (float*)d_out;

    float *w0; __half *wh, *xh;
    cudaGetSymbolAddress((void**)&w0, g_w0);
    cudaGetSymbolAddress((void**)&wh, g_wh);
    cudaGetSymbolAddress((void**)&xh, g_xh);

    prep_kernel<<<193 + 32768, 256>>>(boft_R, perm, (const float4*)x, (uint4*)xh);  // local 0
    cudaFuncSetAttribute(rot01_kernel, cudaFuncAttributeMaxDynamicSharedMemorySize, ROT01_SMEM);
    rot01_kernel<<<dim3(32, 32), 256, ROT01_SMEM>>>(weight, w0);                    // local 1
    rot_kernel<<<dim3(64, 64), 256>>>(w0, nullptr, wh, 2, boft_s);                  // local 2

    cudaFuncSetAttribute(gemm_hmma, cudaFuncAttributeMaxDynamicSharedMemorySize, SMEM_TOTAL);
    gemm_hmma<<<dim3(OUT_F / 128, 16384 / 128), 128, SMEM_TOTAL>>>(xh, wh, bias, out);  // local 3 -> profiled
}

// round 10
// speedup vs baseline: 1.0213x; 1.0213x over previous
#include <cuda_runtime.h>
#include <cuda_fp16.h>
#include <cstdint>

#define IN_F  4096
#define OUT_F 4096
#define NFAC  3

// ---------------- scratch (device globals; allocation forbidden) -----------
__device__ __align__(1024) float  g_Q[NFAC * 64 * 64 * 64];
__device__ int    g_pinv[NFAC * IN_F];
__device__ __align__(1024) float  g_w0[(size_t)OUT_F * IN_F];        // 64 MB
__device__ __align__(1024) float  g_w1[(size_t)OUT_F * IN_F];        // 64 MB
__device__ __align__(1024) __half g_wh[(size_t)OUT_F * IN_F];        // 32 MB
__device__ __align__(1024) __half g_xh[(size_t)8 * 2048 * IN_F];     // 128 MB

// ---------------- helpers ---------------------------------------------------
__device__ __forceinline__ uint32_t smem_u32(const void* p) {
    uint32_t a;
    asm("{ .reg .u64 t; cvta.to.shared.u64 t, %1; cvt.u32.u64 %0, t; }" : "=r"(a) : "l"(p));
    return a;
}
#define CP_ASYNC16(dst, src) \
    asm volatile("cp.async.cg.shared.global [%0], [%1], 16;" :: "r"(dst), "l"(src) : "memory")
#define CP_COMMIT()  asm volatile("cp.async.commit_group;" ::: "memory")
#define CP_WAIT1()   asm volatile("cp.async.wait_group 1;" ::: "memory")

#define LDSM4(r, addr) \
    asm volatile("ldmatrix.sync.aligned.m8n8.x4.shared.b16 {%0,%1,%2,%3}, [%4];" \
        : "=r"((r)[0]), "=r"((r)[1]), "=r"((r)[2]), "=r"((r)[3]) : "r"(addr))

#define MMA16816(c, a, b0v, b1v) \
    asm volatile("mma.sync.aligned.m16n8k16.row.col.f32.f16.f16.f32 " \
        "{%0,%1,%2,%3},{%4,%5,%6,%7},{%8,%9},{%0,%1,%2,%3};" \
        : "+f"((c)[0]), "+f"((c)[1]), "+f"((c)[2]), "+f"((c)[3]) \
        : "r"((a)[0]), "r"((a)[1]), "r"((a)[2]), "r"((a)[3]), "r"(b0v), "r"(b1v))

// ---- fused prep: Cayley (0..191) | pinv (192) | x->fp16 (193..) -----------
__global__ void prep_kernel(const float* __restrict__ R_all,
                            const int* __restrict__ perm,
                            const float4* __restrict__ xin,
                            uint4* __restrict__ xout)
{
    const int tid = threadIdx.x;
    const int bid = blockIdx.x;

    if (bid > 192) {                 // x conversion: one uint4 out per thread
        int i = (bid - 193) * 256 + tid;
        float4 a = xin[2 * i], b = xin[2 * i + 1];
        __half2 h0 = __floats2half2_rn(a.x, a.y);
        __half2 h1 = __floats2half2_rn(a.z, a.w);
        __half2 h2 = __floats2half2_rn(b.x, b.y);
        __half2 h3 = __floats2half2_rn(b.z, b.w);
        uint4 v;
        v.x = *(uint32_t*)&h0; v.y = *(uint32_t*)&h1;
        v.z = *(uint32_t*)&h2; v.w = *(uint32_t*)&h3;
        xout[i] = v;
        return;
    }
    if (bid == 192) {                // inverse permutation
        for (int idx = tid; idx < NFAC * IN_F; idx += 256) {
            int f = idx >> 12, j = idx & 4095;
            g_pinv[(f << 12) + perm[idx]] = j;
        }
        return;
    }

    // Cayley: Q = (I-S)(I+S)^-1 via GJ on [I-S | I+S]
    __shared__ float aug[64][129];
    const float* R = R_all + (size_t)bid * 4096;

    for (int idx = tid; idx < 4096; idx += 256) {
        int i = idx >> 6, j = idx & 63;
        float s = 0.5f * (R[i * 64 + j] - R[j * 64 + i]);
        float d = (i == j) ? 1.0f : 0.0f;
        aug[i][j]      = d - s;
        aug[i][64 + j] = d + s;
    }
    __syncthreads();

    const int r  = tid >> 2;
    const int c0 = tid & 3;
    for (int k = 0; k < 64; k++) {
        float inv = 1.0f / aug[k][k];
        __syncthreads();
        if (tid < 32) {
            #pragma unroll
            for (int i = 0; i < 4; i++) aug[k][tid + 32 * i] *= inv;
        }
        __syncthreads();
        float f = aug[r][k];
        __syncthreads();
        if (r != k) {
            #pragma unroll
            for (int i = 0; i < 32; i++) {
                int c = c0 + 4 * i;
                aug[r][c] -= f * aug[k][c];
            }
        }
        __syncthreads();
    }

    float* Qm = g_Q + (size_t)bid * 4096;
    for (int idx = tid; idx < 4096; idx += 256) {
        int a = idx >> 6, b = idx & 63;
        Qm[a * 64 + b] = aug[b][64 + a];
    }
}

// ---------------- one butterfly factor applied to W columns ----------------
__global__ __launch_bounds__(256) void rot_kernel(
    const float* __restrict__ Win, float* __restrict__ Wout,
    __half* __restrict__ Wh, int factor, const float* __restrict__ s)
{
    __shared__ float Qs[64][68];
    __shared__ float Ts[64][68];
    __shared__ int   cs[64];

    const int d   = blockIdx.x;
    const int rg  = blockIdx.y;
    const int tid = threadIdx.x;

    const float* Qm = g_Q + ((size_t)factor * 64 + d) * 4096;
    #pragma unroll
    for (int i = 0; i < 4; i++) {
        int q = tid + 256 * i;
        int row = q >> 4, c4 = (q & 15) * 4;
        *(float4*)&Qs[row][c4] = *(const float4*)&Qm[row * 64 + c4];
    }
    if (tid < 64) cs[tid] = g_pinv[factor * IN_F + d * 64 + tid];
    __syncthreads();

    const int row0 = rg * 64;
    #pragma unroll
    for (int i = 0; i < 4; i++) {
        int q = tid + 256 * i;
        int rr = q >> 4, b0 = (q & 15) * 4;
        *(float4*)&Ts[rr][b0] = *(const float4*)&Win[(size_t)(row0 + rr) * IN_F + cs[b0]];
    }
    __syncthreads();

    const int a  = tid & 63;
    const int r0 = tid >> 6;
    float acc[16];
    #pragma unroll
    for (int j = 0; j < 16; j++) acc[j] = 0.0f;

    for (int b4 = 0; b4 < 16; b4++) {
        float4 q = *(const float4*)&Qs[a][b4 * 4];
        #pragma unroll
        for (int j = 0; j < 16; j++) {
            float4 t = *(const float4*)&Ts[r0 * 16 + j][b4 * 4];
            acc[j] += q.x * t.x + q.y * t.y + q.z * t.z + q.w * t.w;
        }
    }

    const int col = cs[a];
    #pragma unroll
    for (int j = 0; j < 16; j++) {
        int rr = row0 + r0 * 16 + j;
        if (s) Wh[(size_t)rr * IN_F + col] = __float2half_rn(acc[j] * s[rr]);
        else   Wout[(size_t)rr * IN_F + col] = acc[j];
    }
}

// ---------------- fp16 mma.sync GEMM: C[16384,4096] = A * B^T + bias -------
// CTA 128x128, 4 warps (2x2), warp tile 64x64, BK=64, 3 stages, 2 CTAs/SM.
// NEW: co-resident CTAs (bid vs bid+148, differing in bit 2) start their
// k-loop half a revolution apart so their sync/wait boundaries interleave.
#define BKH 64
#define AST 16384
#define STG 32768
#define STAGES 3
#define SMEM_TOTAL (STAGES * STG)       // 98304

__global__ __launch_bounds__(128, 2) void gemm_hmma(
    const __half* __restrict__ A, const __half* __restrict__ B,
    const float* __restrict__ bias, float* __restrict__ C)
{
    extern __shared__ char smem[];
    const uint32_t sb = smem_u32(smem);
    const int tid = threadIdx.x;
    const int wid = tid >> 5, lid = tid & 31;
    const int wm  = wid >> 1, wn = wid & 1;
    const int m0  = blockIdx.y * 128;
    const int n0  = blockIdx.x * 128;

    const int NK = IN_F / BKH;    // 64
    const int bid = blockIdx.x + (blockIdx.y << 5);
    const int phase = ((bid >> 2) & 1) * (NK / 2);   // decorrelate SM pairs

    float acc[4][4][2][4];
    #pragma unroll
    for (int mi = 0; mi < 4; mi++)
        #pragma unroll
        for (int g = 0; g < 4; g++)
            #pragma unroll
            for (int j = 0; j < 2; j++)
                #pragma unroll
                for (int k = 0; k < 4; k++) acc[mi][g][j][k] = 0.0f;

    auto load_stage = [&](int st, int kt) {
        const uint32_t ab = sb + st * STG;
        const uint32_t bb = ab + AST;
        const __half* Ag = A + (size_t)m0 * IN_F + kt * BKH;
        const __half* Bg = B + (size_t)n0 * IN_F + kt * BKH;
        #pragma unroll
        for (int i = 0; i < 8; i++) {
            int q = tid + 128 * i;
            int r = q >> 3, c = q & 7;
            CP_ASYNC16(ab + r * 128 + ((c ^ (r & 7)) << 4), Ag + (size_t)r * IN_F + c * 8);
        }
        #pragma unroll
        for (int i = 0; i < 8; i++) {
            int q = tid + 128 * i;
            int r = q >> 3, c = q & 7;
            CP_ASYNC16(bb + r * 128 + ((c ^ (r & 7)) << 4), Bg + (size_t)r * IN_F + c * 8);
        }
    };

    load_stage(0, phase);              CP_COMMIT();
    load_stage(1, (1 + phase) & 63);   CP_COMMIT();

    const int lrow = (lid & 7) + ((lid >> 3) & 1) * 8;
    const int lkhi = (lid >> 4) & 1;
    const int rowx = lrow & 7;

    for (int i = 0; i < NK; i++) {
        CP_WAIT1();
        __syncthreads();
        const uint32_t as = sb + (i % STAGES) * STG;
        const uint32_t bs = as + AST;
        const uint32_t a_base = as + (wm * 64 + lrow) * 128;
        const uint32_t b_base = bs + (wn * 64 + lrow) * 128;

        #pragma unroll
        for (int kk = 0; kk < 4; kk++) {
            const uint32_t coff = ((((kk << 1) | lkhi) ^ rowx) << 4);
            uint32_t afr[4][4];
            #pragma unroll
            for (int mi = 0; mi < 4; mi++)
                LDSM4(afr[mi], a_base + mi * 2048 + coff);
            uint32_t bfr[4][4];
            #pragma unroll
            for (int g = 0; g < 4; g++)
                LDSM4(bfr[g], b_base + g * 2048 + coff);
            #pragma unroll
            for (int mi = 0; mi < 4; mi++)
                #pragma unroll
                for (int g = 0; g < 4; g++) {
                    MMA16816(acc[mi][g][0], afr[mi], bfr[g][0], bfr[g][2]);
                    MMA16816(acc[mi][g][1], afr[mi], bfr[g][1], bfr[g][3]);
                }
        }

        if (i + 2 < NK) load_stage((i + 2) % STAGES, (i + 2 + phase) & 63);
        CP_COMMIT();
    }

    // epilogue: fused bias, float2 stores
    const int mrow = lid >> 2;
    const int ncl  = (lid & 3) * 2;
    #pragma unroll
    for (int g = 0; g < 4; g++)
        #pragma unroll
        for (int j = 0; j < 2; j++) {
            int n = n0 + wn * 64 + g * 16 + j * 8 + ncl;
            float2 bv = *(const float2*)&bias[n];
            #pragma unroll
            for (int mi = 0; mi < 4; mi++) {
                int m = m0 + wm * 64 + mi * 16 + mrow;
                float* a4 = acc[mi][g][j];
                float2 v0 = { a4[0] + bv.x, a4[1] + bv.y };
                float2 v1 = { a4[2] + bv.x, a4[3] + bv.y };
                *(float2*)&C[(size_t)m * OUT_F + n]       = v0;
                *(float2*)&C[(size_t)(m + 8) * OUT_F + n] = v1;
            }
        }
}

// ---------------- launch ----------------
extern "C" void kernel_launch(void* const* d_in, const int* in_sizes, int n_in,
                              void* d_out, int out_size)
{
    const float* x      = (const float*)d_in[0];
    const float* weight = (const float*)d_in[1];
    const float* bias   = (const float*)d_in[2];
    const float* boft_R = (const float*)d_in[3];
    const float* boft_s = (const float*)d_in[4];
    const int*   perm   = (const int*)d_in[5];
    float* out = (float*)d_out;

    float *w0, *w1; __half *wh, *xh;
    cudaGetSymbolAddress((void**)&w0, g_w0);
    cudaGetSymbolAddress((void**)&w1, g_w1);
    cudaGetSymbolAddress((void**)&wh, g_wh);
    cudaGetSymbolAddress((void**)&xh, g_xh);

    prep_kernel<<<193 + 32768, 256>>>(boft_R, perm, (const float4*)x, (uint4*)xh);
    rot_kernel<<<dim3(64, 64), 256>>>(weight, w0, nullptr, 0, nullptr);
    rot_kernel<<<dim3(64, 64), 256>>>(w0,     w1, nullptr, 1, nullptr);
    rot_kernel<<<dim3(64, 64), 256>>>(w1, nullptr, wh,     2, boft_s);

    cudaFuncSetAttribute(gemm_hmma, cudaFuncAttributeMaxDynamicSharedMemorySize, SMEM_TOTAL);
    gemm_hmma<<<dim3(OUT_F / 128, 16384 / 128), 128, SMEM_TOTAL>>>(xh, wh, bias, out);
}

// round 11
// speedup vs baseline: 1.0340x; 1.0124x over previous
#include <cuda_runtime.h>
#include <cuda_fp16.h>
#include <cstdint>

#define IN_F  4096
#define OUT_F 4096
#define NFAC  3

// ---------------- scratch (device globals; allocation forbidden) -----------
__device__ __align__(1024) float  g_Q[NFAC * 64 * 64 * 64];
__device__ int    g_pinv[NFAC * IN_F];
__device__ __align__(1024) float  g_w0[(size_t)OUT_F * IN_F];        // 64 MB
__device__ __align__(1024) float  g_w1[(size_t)OUT_F * IN_F];        // 64 MB
__device__ __align__(1024) __half g_wh[(size_t)OUT_F * IN_F];        // 32 MB
__device__ __align__(1024) __half g_xh[(size_t)8 * 2048 * IN_F];     // 128 MB

// ---------------- helpers ---------------------------------------------------
__device__ __forceinline__ uint32_t smem_u32(const void* p) {
    uint32_t a;
    asm("{ .reg .u64 t; cvta.to.shared.u64 t, %1; cvt.u32.u64 %0, t; }" : "=r"(a) : "l"(p));
    return a;
}
#define CP_ASYNC16(dst, src) \
    asm volatile("cp.async.cg.shared.global [%0], [%1], 16;" :: "r"(dst), "l"(src) : "memory")
#define CP_COMMIT()  asm volatile("cp.async.commit_group;" ::: "memory")
#define CP_WAIT1()   asm volatile("cp.async.wait_group 1;" ::: "memory")

#define LDSM4(r, addr) \
    asm volatile("ldmatrix.sync.aligned.m8n8.x4.shared.b16 {%0,%1,%2,%3}, [%4];" \
        : "=r"((r)[0]), "=r"((r)[1]), "=r"((r)[2]), "=r"((r)[3]) : "r"(addr))

#define MMA16816(c, a, b0v, b1v) \
    asm volatile("mma.sync.aligned.m16n8k16.row.col.f32.f16.f16.f32 " \
        "{%0,%1,%2,%3},{%4,%5,%6,%7},{%8,%9},{%0,%1,%2,%3};" \
        : "+f"((c)[0]), "+f"((c)[1]), "+f"((c)[2]), "+f"((c)[3]) \
        : "r"((a)[0]), "r"((a)[1]), "r"((a)[2]), "r"((a)[3]), "r"(b0v), "r"(b1v))

// ---- fused prep: Cayley (0..191) | pinv (192) | x->fp16 (193..) -----------
__global__ void prep_kernel(const float* __restrict__ R_all,
                            const int* __restrict__ perm,
                            const float4* __restrict__ xin,
                            uint4* __restrict__ xout)
{
    const int tid = threadIdx.x;
    const int bid = blockIdx.x;

    if (bid > 192) {                 // x conversion: one uint4 out per thread
        int i = (bid - 193) * 256 + tid;
        float4 a = xin[2 * i], b = xin[2 * i + 1];
        __half2 h0 = __floats2half2_rn(a.x, a.y);
        __half2 h1 = __floats2half2_rn(a.z, a.w);
        __half2 h2 = __floats2half2_rn(b.x, b.y);
        __half2 h3 = __floats2half2_rn(b.z, b.w);
        uint4 v;
        v.x = *(uint32_t*)&h0; v.y = *(uint32_t*)&h1;
        v.z = *(uint32_t*)&h2; v.w = *(uint32_t*)&h3;
        xout[i] = v;
        return;
    }
    if (bid == 192) {                // inverse permutation
        for (int idx = tid; idx < NFAC * IN_F; idx += 256) {
            int f = idx >> 12, j = idx & 4095;
            g_pinv[(f << 12) + perm[idx]] = j;
        }
        return;
    }

    // Cayley: Q = (I-S)(I+S)^-1 via GJ on [I-S | I+S]
    __shared__ float aug[64][129];
    const float* R = R_all + (size_t)bid * 4096;

    for (int idx = tid; idx < 4096; idx += 256) {
        int i = idx >> 6, j = idx & 63;
        float s = 0.5f * (R[i * 64 + j] - R[j * 64 + i]);
        float d = (i == j) ? 1.0f : 0.0f;
        aug[i][j]      = d - s;
        aug[i][64 + j] = d + s;
    }
    __syncthreads();

    const int r  = tid >> 2;
    const int c0 = tid & 3;
    for (int k = 0; k < 64; k++) {
        float inv = 1.0f / aug[k][k];
        __syncthreads();
        if (tid < 32) {
            #pragma unroll
            for (int i = 0; i < 4; i++) aug[k][tid + 32 * i] *= inv;
        }
        __syncthreads();
        float f = aug[r][k];
        __syncthreads();
        if (r != k) {
            #pragma unroll
            for (int i = 0; i < 32; i++) {
                int c = c0 + 4 * i;
                aug[r][c] -= f * aug[k][c];
            }
        }
        __syncthreads();
    }

    float* Qm = g_Q + (size_t)bid * 4096;
    for (int idx = tid; idx < 4096; idx += 256) {
        int a = idx >> 6, b = idx & 63;
        Qm[a * 64 + b] = aug[b][64 + a];
    }
}

// ---------------- one butterfly factor applied to W columns ----------------
__global__ __launch_bounds__(256) void rot_kernel(
    const float* __restrict__ Win, float* __restrict__ Wout,
    __half* __restrict__ Wh, int factor, const float* __restrict__ s)
{
    __shared__ float Qs[64][68];
    __shared__ float Ts[64][68];
    __shared__ int   cs[64];

    const int d   = blockIdx.x;
    const int rg  = blockIdx.y;
    const int tid = threadIdx.x;

    const float* Qm = g_Q + ((size_t)factor * 64 + d) * 4096;
    #pragma unroll
    for (int i = 0; i < 4; i++) {
        int q = tid + 256 * i;
        int row = q >> 4, c4 = (q & 15) * 4;
        *(float4*)&Qs[row][c4] = *(const float4*)&Qm[row * 64 + c4];
    }
    if (tid < 64) cs[tid] = g_pinv[factor * IN_F + d * 64 + tid];
    __syncthreads();

    const int row0 = rg * 64;
    #pragma unroll
    for (int i = 0; i < 4; i++) {
        int q = tid + 256 * i;
        int rr = q >> 4, b0 = (q & 15) * 4;
        *(float4*)&Ts[rr][b0] = *(const float4*)&Win[(size_t)(row0 + rr) * IN_F + cs[b0]];
    }
    __syncthreads();

    const int a  = tid & 63;
    const int r0 = tid >> 6;
    float acc[16];
    #pragma unroll
    for (int j = 0; j < 16; j++) acc[j] = 0.0f;

    for (int b4 = 0; b4 < 16; b4++) {
        float4 q = *(const float4*)&Qs[a][b4 * 4];
        #pragma unroll
        for (int j = 0; j < 16; j++) {
            float4 t = *(const float4*)&Ts[r0 * 16 + j][b4 * 4];
            acc[j] += q.x * t.x + q.y * t.y + q.z * t.z + q.w * t.w;
        }
    }

    const int col = cs[a];
    #pragma unroll
    for (int j = 0; j < 16; j++) {
        int rr = row0 + r0 * 16 + j;
        if (s) Wh[(size_t)rr * IN_F + col] = __float2half_rn(acc[j] * s[rr]);
        else   Wout[(size_t)rr * IN_F + col] = acc[j];
    }
}

// ---------------- fp16 mma.sync GEMM: C[16384,4096] = A * B^T + bias -------
// CTA 128x128, 4 warps (2x2), warp tile 64x64, BK=64, 3 stages, 2 CTAs/SM.
// NEW (isolated): kk-level fragment double-buffering; load_stage position
// unchanged from the proven R5/R7 loop.
#define BKH 64
#define AST 16384
#define STG 32768
#define STAGES 3
#define SMEM_TOTAL (STAGES * STG)       // 98304

__global__ __launch_bounds__(128, 2) void gemm_hmma(
    const __half* __restrict__ A, const __half* __restrict__ B,
    const float* __restrict__ bias, float* __restrict__ C)
{
    extern __shared__ char smem[];
    const uint32_t sb = smem_u32(smem);
    const int tid = threadIdx.x;
    const int wid = tid >> 5, lid = tid & 31;
    const int wm  = wid >> 1, wn = wid & 1;
    const int m0  = blockIdx.y * 128;
    const int n0  = blockIdx.x * 128;

    float acc[4][4][2][4];
    #pragma unroll
    for (int mi = 0; mi < 4; mi++)
        #pragma unroll
        for (int g = 0; g < 4; g++)
            #pragma unroll
            for (int j = 0; j < 2; j++)
                #pragma unroll
                for (int k = 0; k < 4; k++) acc[mi][g][j][k] = 0.0f;

    auto load_stage = [&](int st, int kt) {
        const uint32_t ab = sb + st * STG;
        const uint32_t bb = ab + AST;
        const __half* Ag = A + (size_t)m0 * IN_F + kt * BKH;
        const __half* Bg = B + (size_t)n0 * IN_F + kt * BKH;
        #pragma unroll
        for (int i = 0; i < 8; i++) {
            int q = tid + 128 * i;
            int r = q >> 3, c = q & 7;
            CP_ASYNC16(ab + r * 128 + ((c ^ (r & 7)) << 4), Ag + (size_t)r * IN_F + c * 8);
        }
        #pragma unroll
        for (int i = 0; i < 8; i++) {
            int q = tid + 128 * i;
            int r = q >> 3, c = q & 7;
            CP_ASYNC16(bb + r * 128 + ((c ^ (r & 7)) << 4), Bg + (size_t)r * IN_F + c * 8);
        }
    };

    load_stage(0, 0); CP_COMMIT();
    load_stage(1, 1); CP_COMMIT();

    const int lrow = (lid & 7) + ((lid >> 3) & 1) * 8;
    const int lkhi = (lid >> 4) & 1;
    const int rowx = lrow & 7;

    const int NK = IN_F / BKH;    // 64
    for (int kt = 0; kt < NK; kt++) {
        CP_WAIT1();
        __syncthreads();
        const uint32_t as = sb + (kt % STAGES) * STG;
        const uint32_t bs = as + AST;
        const uint32_t a_base = as + (wm * 64 + lrow) * 128;
        const uint32_t b_base = bs + (wn * 64 + lrow) * 128;

        uint32_t afr[2][4][4], bfr[2][4][4];
        // prefetch kk = 0 fragments
        {
            const uint32_t coff = ((lkhi ^ rowx) << 4);
            #pragma unroll
            for (int mi = 0; mi < 4; mi++) LDSM4(afr[0][mi], a_base + mi * 2048 + coff);
            #pragma unroll
            for (int g = 0; g < 4; g++)    LDSM4(bfr[0][g],  b_base + g * 2048 + coff);
        }

        #pragma unroll
        for (int kk = 0; kk < 4; kk++) {
            const int cur = kk & 1, nxt = cur ^ 1;
            if (kk < 3) {       // prefetch kk+1 while kk's MMAs run
                const uint32_t coff = (((((kk + 1) << 1) | lkhi) ^ rowx) << 4);
                #pragma unroll
                for (int mi = 0; mi < 4; mi++)
                    LDSM4(afr[nxt][mi], a_base + mi * 2048 + coff);
                #pragma unroll
                for (int g = 0; g < 4; g++)
                    LDSM4(bfr[nxt][g],  b_base + g * 2048 + coff);
            }
            #pragma unroll
            for (int mi = 0; mi < 4; mi++)
                #pragma unroll
                for (int g = 0; g < 4; g++) {
                    MMA16816(acc[mi][g][0], afr[cur][mi], bfr[cur][g][0], bfr[cur][g][2]);
                    MMA16816(acc[mi][g][1], afr[cur][mi], bfr[cur][g][1], bfr[cur][g][3]);
                }
        }

        if (kt + 2 < NK) load_stage((kt + 2) % STAGES, kt + 2);
        CP_COMMIT();
    }

    // epilogue: fused bias, float2 stores
    const int mrow = lid >> 2;
    const int ncl  = (lid & 3) * 2;
    #pragma unroll
    for (int g = 0; g < 4; g++)
        #pragma unroll
        for (int j = 0; j < 2; j++) {
            int n = n0 + wn * 64 + g * 16 + j * 8 + ncl;
            float2 bv = *(const float2*)&bias[n];
            #pragma unroll
            for (int mi = 0; mi < 4; mi++) {
                int m = m0 + wm * 64 + mi * 16 + mrow;
                float* a4 = acc[mi][g][j];
                float2 v0 = { a4[0] + bv.x, a4[1] + bv.y };
                float2 v1 = { a4[2] + bv.x, a4[3] + bv.y };
                *(float2*)&C[(size_t)m * OUT_F + n]       = v0;
                *(float2*)&C[(size_t)(m + 8) * OUT_F + n] = v1;
            }
        }
}

// ---------------- launch ----------------
extern "C" void kernel_launch(void* const* d_in, const int* in_sizes, int n_in,
                              void* d_out, int out_size)
{
    const float* x      = (const float*)d_in[0];
    const float* weight = (const float*)d_in[1];
    const float* bias   = (const float*)d_in[2];
    const float* boft_R = (const float*)d_in[3];
    const float* boft_s = (const float*)d_in[4];
    const int*   perm   = (const int*)d_in[5];
    float* out = (float*)d_out;

    float *w0, *w1; __half *wh, *xh;
    cudaGetSymbolAddress((void**)&w0, g_w0);
    cudaGetSymbolAddress((void**)&w1, g_w1);
    cudaGetSymbolAddress((void**)&wh, g_wh);
    cudaGetSymbolAddress((void**)&xh, g_xh);

    prep_kernel<<<193 + 32768, 256>>>(boft_R, perm, (const float4*)x, (uint4*)xh);
    rot_kernel<<<dim3(64, 64), 256>>>(weight, w0, nullptr, 0, nullptr);
    rot_kernel<<<dim3(64, 64), 256>>>(w0,     w1, nullptr, 1, nullptr);
    rot_kernel<<<dim3(64, 64), 256>>>(w1, nullptr, wh,     2, boft_s);

    cudaFuncSetAttribute(gemm_hmma, cudaFuncAttributeMaxDynamicSharedMemorySize, SMEM_TOTAL);
    gemm_hmma<<<dim3(OUT_F / 128, 16384 / 128), 128, SMEM_TOTAL>>>(xh, wh, bias, out);
}

// round 12
// speedup vs baseline: 1.1399x; 1.1024x over previous
#include <cuda_runtime.h>
#include <cuda_fp16.h>
#include <cstdint>

#define IN_F  4096
#define OUT_F 4096
#define NFAC  3

// ---------------- scratch (device globals; allocation forbidden) -----------
__device__ __align__(1024) float  g_Q[NFAC * 64 * 64 * 64];
__device__ int    g_pinv[NFAC * IN_F];
__device__ __align__(1024) __half g_hA[(size_t)OUT_F * IN_F];        // 32 MB
__device__ __align__(1024) __half g_hB[(size_t)OUT_F * IN_F];        // 32 MB
__device__ __align__(1024) __half g_xh[(size_t)8 * 2048 * IN_F];     // 128 MB

// ---------------- helpers ---------------------------------------------------
__device__ __forceinline__ uint32_t smem_u32(const void* p) {
    uint32_t a;
    asm("{ .reg .u64 t; cvta.to.shared.u64 t, %1; cvt.u32.u64 %0, t; }" : "=r"(a) : "l"(p));
    return a;
}
#define CP_ASYNC16(dst, src) \
    asm volatile("cp.async.cg.shared.global [%0], [%1], 16;" :: "r"(dst), "l"(src) : "memory")
#define CP_COMMIT()  asm volatile("cp.async.commit_group;" ::: "memory")
#define CP_WAIT1()   asm volatile("cp.async.wait_group 1;" ::: "memory")

#define LDSM4(r, addr) \
    asm volatile("ldmatrix.sync.aligned.m8n8.x4.shared.b16 {%0,%1,%2,%3}, [%4];" \
        : "=r"((r)[0]), "=r"((r)[1]), "=r"((r)[2]), "=r"((r)[3]) : "r"(addr))

#define MMA16816(c, a, b0v, b1v) \
    asm volatile("mma.sync.aligned.m16n8k16.row.col.f32.f16.f16.f32 " \
        "{%0,%1,%2,%3},{%4,%5,%6,%7},{%8,%9},{%0,%1,%2,%3};" \
        : "+f"((c)[0]), "+f"((c)[1]), "+f"((c)[2]), "+f"((c)[3]) \
        : "r"((a)[0]), "r"((a)[1]), "r"((a)[2]), "r"((a)[3]), "r"(b0v), "r"(b1v))

// ---- fused prep: Cayley (0..191) | pinv (192) | x->fp16 (193..) -----------
__global__ void prep_kernel(const float* __restrict__ R_all,
                            const int* __restrict__ perm,
                            const float4* __restrict__ xin,
                            uint4* __restrict__ xout)
{
    const int tid = threadIdx.x;
    const int bid = blockIdx.x;

    if (bid > 192) {                 // x conversion: one uint4 out per thread
        int i = (bid - 193) * 256 + tid;
        float4 a = xin[2 * i], b = xin[2 * i + 1];
        __half2 h0 = __floats2half2_rn(a.x, a.y);
        __half2 h1 = __floats2half2_rn(a.z, a.w);
        __half2 h2 = __floats2half2_rn(b.x, b.y);
        __half2 h3 = __floats2half2_rn(b.z, b.w);
        uint4 v;
        v.x = *(uint32_t*)&h0; v.y = *(uint32_t*)&h1;
        v.z = *(uint32_t*)&h2; v.w = *(uint32_t*)&h3;
        xout[i] = v;
        return;
    }
    if (bid == 192) {                // inverse permutation
        for (int idx = tid; idx < NFAC * IN_F; idx += 256) {
            int f = idx >> 12, j = idx & 4095;
            g_pinv[(f << 12) + perm[idx]] = j;
        }
        return;
    }

    // Cayley: Q = (I-S)(I+S)^-1 via GJ on [I-S | I+S]
    __shared__ float aug[64][129];
    const float* R = R_all + (size_t)bid * 4096;

    for (int idx = tid; idx < 4096; idx += 256) {
        int i = idx >> 6, j = idx & 63;
        float s = 0.5f * (R[i * 64 + j] - R[j * 64 + i]);
        float d = (i == j) ? 1.0f : 0.0f;
        aug[i][j]      = d - s;
        aug[i][64 + j] = d + s;
    }
    __syncthreads();

    const int r  = tid >> 2;
    const int c0 = tid & 3;
    for (int k = 0; k < 64; k++) {
        float inv = 1.0f / aug[k][k];
        __syncthreads();
        if (tid < 32) {
            #pragma unroll
            for (int i = 0; i < 4; i++) aug[k][tid + 32 * i] *= inv;
        }
        __syncthreads();
        float f = aug[r][k];
        __syncthreads();
        if (r != k) {
            #pragma unroll
            for (int i = 0; i < 32; i++) {
                int c = c0 + 4 * i;
                aug[r][c] -= f * aug[k][c];
            }
        }
        __syncthreads();
    }

    float* Qm = g_Q + (size_t)bid * 4096;
    for (int idx = tid; idx < 4096; idx += 256) {
        int a = idx >> 6, b = idx & 63;
        Qm[a * 64 + b] = aug[b][64 + a];
    }
}

// ------- one butterfly factor via HMMA: Wout = Wblock(128x64) * Q^T --------
// Gather/scatter columns by pinv at the smem boundary (runs of 32 keep all
// global accesses 16B-vectorizable). fp16 operands, fp32 accumulate.
// Pass 0 converts fp32 weight; last pass multiplies rows by s.
__global__ __launch_bounds__(256) void rot_hmma(
    const float* __restrict__ WinF, const __half* __restrict__ WinH,
    __half* __restrict__ Wout, int factor, const float* __restrict__ s)
{
    __shared__ __align__(16) char sm[128 * 128 + 64 * 128];   // A tile + Q tile
    __shared__ int   cs[64];
    __shared__ float sv[128];
    const uint32_t sa = smem_u32(sm);
    const uint32_t sq = sa + 128 * 128;

    const int d    = blockIdx.x;      // 64-col block
    const int rg   = blockIdx.y;      // 128-row group
    const int tid  = threadIdx.x;
    const int row0 = rg * 128;

    if (tid < 64) cs[tid] = g_pinv[factor * IN_F + d * 64 + tid];
    if (s != nullptr && tid < 128) sv[tid] = s[row0 + tid];
    __syncthreads();

    // A tile: 128 rows x 64 halves (128B rows, XOR-swizzled 16B chunks)
    #pragma unroll
    for (int i = 0; i < 4; i++) {
        int q = tid + 256 * i;                    // 1024 chunks of 16B
        int r = q >> 3, c = q & 7;
        char* dst = sm + r * 128 + ((c ^ (r & 7)) << 4);
        int b0 = c * 8;                           // 8-aligned -> inside a run
        if (WinF) {
            const float* src = &WinF[(size_t)(row0 + r) * IN_F + cs[b0]];
            float4 v0 = *(const float4*)src;
            float4 v1 = *(const float4*)(src + 4);
            __half2 h0 = __floats2half2_rn(v0.x, v0.y);
            __half2 h1 = __floats2half2_rn(v0.z, v0.w);
            __half2 h2 = __floats2half2_rn(v1.x, v1.y);
            __half2 h3 = __floats2half2_rn(v1.z, v1.w);
            uint4 u;
            u.x = *(uint32_t*)&h0; u.y = *(uint32_t*)&h1;
            u.z = *(uint32_t*)&h2; u.w = *(uint32_t*)&h3;
            *(uint4*)dst = u;
        } else {
            *(uint4*)dst = *(const uint4*)&WinH[(size_t)(row0 + r) * IN_F + cs[b0]];
        }
    }

    // Q tile: 64 rows (a) x 64 halves (b), same layout; convert fp32 -> fp16
    const float* Qm = g_Q + ((size_t)factor * 64 + d) * 4096;
    #pragma unroll
    for (int i = 0; i < 2; i++) {
        int q = tid + 256 * i;                    // 512 chunks of 16B
        int r = q >> 3, c = q & 7;
        const float* src = &Qm[r * 64 + c * 8];
        float4 v0 = *(const float4*)src;
        float4 v1 = *(const float4*)(src + 4);
        __half2 h0 = __floats2half2_rn(v0.x, v0.y);
        __half2 h1 = __floats2half2_rn(v0.z, v0.w);
        __half2 h2 = __floats2half2_rn(v1.x, v1.y);
        __half2 h3 = __floats2half2_rn(v1.z, v1.w);
        uint4 u;
        u.x = *(uint32_t*)&h0; u.y = *(uint32_t*)&h1;
        u.z = *(uint32_t*)&h2; u.w = *(uint32_t*)&h3;
        *(uint4*)(sm + 128 * 128 + r * 128 + ((c ^ (r & 7)) << 4)) = u;
    }
    __syncthreads();

    // MMA: warp w computes rows [w*16, w*16+16) x all 64 cols
    const int wid = tid >> 5, lid = tid & 31;
    const int lrow = (lid & 7) + ((lid >> 3) & 1) * 8;
    const int lkhi = (lid >> 4) & 1;
    const int rowx = lrow & 7;
    const uint32_t a_base = sa + (wid * 16 + lrow) * 128;
    const uint32_t b_base = sq + lrow * 128;

    float acc[4][2][4];
    #pragma unroll
    for (int g = 0; g < 4; g++)
        #pragma unroll
        for (int j = 0; j < 2; j++)
            #pragma unroll
            for (int k = 0; k < 4; k++) acc[g][j][k] = 0.0f;

    #pragma unroll
    for (int kk = 0; kk < 4; kk++) {
        const uint32_t coff = ((((kk << 1) | lkhi) ^ rowx) << 4);
        uint32_t afr[4];
        LDSM4(afr, a_base + coff);
        uint32_t bfr[4][4];
        #pragma unroll
        for (int g = 0; g < 4; g++)
            LDSM4(bfr[g], b_base + g * 2048 + coff);
        #pragma unroll
        for (int g = 0; g < 4; g++) {
            MMA16816(acc[g][0], afr, bfr[g][0], bfr[g][2]);
            MMA16816(acc[g][1], afr, bfr[g][1], bfr[g][3]);
        }
    }

    // epilogue: scale (last pass), fp16 pack, scatter cols via cs
    const int mrow = lid >> 2;
    const int ncl  = (lid & 3) * 2;
    const int mloc0 = wid * 16 + mrow;
    float s0 = 1.0f, s1 = 1.0f;
    if (s != nullptr) { s0 = sv[mloc0]; s1 = sv[mloc0 + 8]; }
    #pragma unroll
    for (int g = 0; g < 4; g++)
        #pragma unroll
        for (int j = 0; j < 2; j++) {
            int n = g * 16 + j * 8 + ncl;
            int gcol = cs[n];                    // cs[n+1] == gcol+1 (run of 32)
            float* a4 = acc[g][j];
            __half2 h0 = __floats2half2_rn(a4[0] * s0, a4[1] * s0);
            __half2 h1 = __floats2half2_rn(a4[2] * s1, a4[3] * s1);
            *(__half2*)&Wout[(size_t)(row0 + mloc0) * IN_F + gcol]     = h0;
            *(__half2*)&Wout[(size_t)(row0 + mloc0 + 8) * IN_F + gcol] = h1;
        }
}

// ---------------- fp16 mma.sync GEMM: C[16384,4096] = A * B^T + bias -------
// CTA 128x128, 4 warps (2x2), warp tile 64x64, BK=64, 3 stages, 2 CTAs/SM.
// Proven R5/R7 loop structure.
#define BKH 64
#define AST 16384
#define STG 32768
#define STAGES 3
#define SMEM_TOTAL (STAGES * STG)       // 98304

__global__ __launch_bounds__(128, 2) void gemm_hmma(
    const __half* __restrict__ A, const __half* __restrict__ B,
    const float* __restrict__ bias, float* __restrict__ C)
{
    extern __shared__ char smem[];
    const uint32_t sb = smem_u32(smem);
    const int tid = threadIdx.x;
    const int wid = tid >> 5, lid = tid & 31;
    const int wm  = wid >> 1, wn = wid & 1;
    const int m0  = blockIdx.y * 128;
    const int n0  = blockIdx.x * 128;

    float acc[4][4][2][4];
    #pragma unroll
    for (int mi = 0; mi < 4; mi++)
        #pragma unroll
        for (int g = 0; g < 4; g++)
            #pragma unroll
            for (int j = 0; j < 2; j++)
                #pragma unroll
                for (int k = 0; k < 4; k++) acc[mi][g][j][k] = 0.0f;

    auto load_stage = [&](int st, int kt) {
        const uint32_t ab = sb + st * STG;
        const uint32_t bb = ab + AST;
        const __half* Ag = A + (size_t)m0 * IN_F + kt * BKH;
        const __half* Bg = B + (size_t)n0 * IN_F + kt * BKH;
        #pragma unroll
        for (int i = 0; i < 8; i++) {
            int q = tid + 128 * i;
            int r = q >> 3, c = q & 7;
            CP_ASYNC16(ab + r * 128 + ((c ^ (r & 7)) << 4), Ag + (size_t)r * IN_F + c * 8);
        }
        #pragma unroll
        for (int i = 0; i < 8; i++) {
            int q = tid + 128 * i;
            int r = q >> 3, c = q & 7;
            CP_ASYNC16(bb + r * 128 + ((c ^ (r & 7)) << 4), Bg + (size_t)r * IN_F + c * 8);
        }
    };

    load_stage(0, 0); CP_COMMIT();
    load_stage(1, 1); CP_COMMIT();

    const int lrow = (lid & 7) + ((lid >> 3) & 1) * 8;
    const int lkhi = (lid >> 4) & 1;
    const int rowx = lrow & 7;

    const int NK = IN_F / BKH;    // 64
    for (int kt = 0; kt < NK; kt++) {
        CP_WAIT1();
        __syncthreads();
        const uint32_t as = sb + (kt % STAGES) * STG;
        const uint32_t bs = as + AST;
        const uint32_t a_base = as + (wm * 64 + lrow) * 128;
        const uint32_t b_base = bs + (wn * 64 + lrow) * 128;

        #pragma unroll
        for (int kk = 0; kk < 4; kk++) {
            const uint32_t coff = ((((kk << 1) | lkhi) ^ rowx) << 4);
            uint32_t afr[4][4];
            #pragma unroll
            for (int mi = 0; mi < 4; mi++)
                LDSM4(afr[mi], a_base + mi * 2048 + coff);
            uint32_t bfr[4][4];
            #pragma unroll
            for (int g = 0; g < 4; g++)
                LDSM4(bfr[g], b_base + g * 2048 + coff);
            #pragma unroll
            for (int mi = 0; mi < 4; mi++)
                #pragma unroll
                for (int g = 0; g < 4; g++) {
                    MMA16816(acc[mi][g][0], afr[mi], bfr[g][0], bfr[g][2]);
                    MMA16816(acc[mi][g][1], afr[mi], bfr[g][1], bfr[g][3]);
                }
        }

        if (kt + 2 < NK) load_stage((kt + 2) % STAGES, kt + 2);
        CP_COMMIT();
    }

    // epilogue: fused bias, float2 stores
    const int mrow = lid >> 2;
    const int ncl  = (lid & 3) * 2;
    #pragma unroll
    for (int g = 0; g < 4; g++)
        #pragma unroll
        for (int j = 0; j < 2; j++) {
            int n = n0 + wn * 64 + g * 16 + j * 8 + ncl;
            float2 bv = *(const float2*)&bias[n];
            #pragma unroll
            for (int mi = 0; mi < 4; mi++) {
                int m = m0 + wm * 64 + mi * 16 + mrow;
                float* a4 = acc[mi][g][j];
                float2 v0 = { a4[0] + bv.x, a4[1] + bv.y };
                float2 v1 = { a4[2] + bv.x, a4[3] + bv.y };
                *(float2*)&C[(size_t)m * OUT_F + n]       = v0;
                *(float2*)&C[(size_t)(m + 8) * OUT_F + n] = v1;
            }
        }
}

// ---------------- launch ----------------
extern "C" void kernel_launch(void* const* d_in, const int* in_sizes, int n_in,
                              void* d_out, int out_size)
{
    const float* x      = (const float*)d_in[0];
    const float* weight = (const float*)d_in[1];
    const float* bias   = (const float*)d_in[2];
    const float* boft_R = (const float*)d_in[3];
    const float* boft_s = (const float*)d_in[4];
    const int*   perm   = (const int*)d_in[5];
    float* out = (float*)d_out;

    __half *hA, *hB, *xh;
    cudaGetSymbolAddress((void**)&hA, g_hA);
    cudaGetSymbolAddress((void**)&hB, g_hB);
    cudaGetSymbolAddress((void**)&xh, g_xh);

    prep_kernel<<<193 + 32768, 256>>>(boft_R, perm, (const float4*)x, (uint4*)xh);
    rot_hmma<<<dim3(64, 32), 256>>>(weight,  nullptr, hA, 0, nullptr);
    rot_hmma<<<dim3(64, 32), 256>>>(nullptr, hA,      hB, 1, nullptr);
    rot_hmma<<<dim3(64, 32), 256>>>(nullptr, hB,      hA, 2, boft_s);

    cudaFuncSetAttribute(gemm_hmma, cudaFuncAttributeMaxDynamicSharedMemorySize, SMEM_TOTAL);
    gemm_hmma<<<dim3(OUT_F / 128, 16384 / 128), 128, SMEM_TOTAL>>>(xh, hA, bias, out);
}